// round 1
// baseline (speedup 1.0000x reference)
#include <cuda_runtime.h>

#define BH     64
#define SEQ    8192
#define DIM    64
#define NCHUNK 8
#define CHUNK  (SEQ / NCHUNK)   // 1024
#define TS     32               // s-rows per smem tile in phase 1
#define P2ROWS 64               // s-rows per block in phase 2

// Scratch (allocation-free: __device__ globals)
__device__ float g_kv_part[BH * NCHUNK * DIM * DIM];  // 8 MB
__device__ float g_ks_part[BH * NCHUNK * DIM];
__device__ float g_kv[BH * DIM * DIM];                // 1 MB
__device__ float g_ks[BH * DIM];

// ---------------------------------------------------------------------------
// Phase 1: per-(head, chunk) partial kv = relu(K)^T @ V  and ksum = sum relu(K)
// Block: 128 threads, thread tile 4(d) x 8(e).
// ---------------------------------------------------------------------------
__global__ __launch_bounds__(128) void la_phase1(const float* __restrict__ K,
                                                 const float* __restrict__ V) {
    const int bh    = blockIdx.x;
    const int chunk = blockIdx.y;
    const float* Kh = K + (size_t)bh * SEQ * DIM + (size_t)chunk * CHUNK * DIM;
    const float* Vh = V + (size_t)bh * SEQ * DIM + (size_t)chunk * CHUNK * DIM;

    __shared__ float Ks[TS][DIM];
    __shared__ float Vs[TS][DIM];

    const int tid = threadIdx.x;
    const int tx  = tid & 7;    // e group: cols tx*8 .. tx*8+7
    const int ty  = tid >> 3;   // d group: rows ty*4 .. ty*4+3 (0..15)

    float acc[4][8];
#pragma unroll
    for (int i = 0; i < 4; i++)
#pragma unroll
        for (int j = 0; j < 8; j++) acc[i][j] = 0.f;
    float ks = 0.f;

    for (int s0 = 0; s0 < CHUNK; s0 += TS) {
        // Stage TS x 64 of K (with relu) and V. 512 float4 per array / 128 thr = 4 each.
#pragma unroll
        for (int l = 0; l < 4; l++) {
            int idx = l * 128 + tid;   // float4 index in tile
            int row = idx >> 4;        // 16 float4 per row
            int c4  = idx & 15;
            float4 kk = ((const float4*)(Kh + (size_t)(s0 + row) * DIM))[c4];
            kk.x = fmaxf(kk.x, 0.f); kk.y = fmaxf(kk.y, 0.f);
            kk.z = fmaxf(kk.z, 0.f); kk.w = fmaxf(kk.w, 0.f);
            ((float4*)&Ks[row][0])[c4] = kk;
            ((float4*)&Vs[row][0])[c4] = ((const float4*)(Vh + (size_t)(s0 + row) * DIM))[c4];
        }
        __syncthreads();

#pragma unroll
        for (int s = 0; s < TS; s++) {
            float4 k4 = *(const float4*)&Ks[s][ty * 4];
            float4 va = *(const float4*)&Vs[s][tx * 8];
            float4 vb = *(const float4*)&Vs[s][tx * 8 + 4];
            float kk[4] = {k4.x, k4.y, k4.z, k4.w};
            float vv[8] = {va.x, va.y, va.z, va.w, vb.x, vb.y, vb.z, vb.w};
#pragma unroll
            for (int i = 0; i < 4; i++)
#pragma unroll
                for (int j = 0; j < 8; j++)
                    acc[i][j] = fmaf(kk[i], vv[j], acc[i][j]);
        }
        if (tid < DIM) {
#pragma unroll
            for (int s = 0; s < TS; s++) ks += Ks[s][tid];
        }
        __syncthreads();
    }

    float* kvp = g_kv_part + (size_t)(bh * NCHUNK + chunk) * DIM * DIM;
#pragma unroll
    for (int i = 0; i < 4; i++) {
        int d = ty * 4 + i;
        float4 w0 = make_float4(acc[i][0], acc[i][1], acc[i][2], acc[i][3]);
        float4 w1 = make_float4(acc[i][4], acc[i][5], acc[i][6], acc[i][7]);
        *(float4*)&kvp[d * DIM + tx * 8]     = w0;
        *(float4*)&kvp[d * DIM + tx * 8 + 4] = w1;
    }
    if (tid < DIM) g_ks_part[(bh * NCHUNK + chunk) * DIM + tid] = ks;
}

// ---------------------------------------------------------------------------
// Reduce partials -> g_kv, g_ks
// ---------------------------------------------------------------------------
__global__ __launch_bounds__(256) void la_reduce() {
    const int bh  = blockIdx.x;
    const int tid = threadIdx.x;
    for (int idx = tid; idx < DIM * DIM; idx += 256) {
        float sum = 0.f;
#pragma unroll
        for (int c = 0; c < NCHUNK; c++)
            sum += g_kv_part[(size_t)(bh * NCHUNK + c) * DIM * DIM + idx];
        g_kv[(size_t)bh * DIM * DIM + idx] = sum;
    }
    if (tid < DIM) {
        float s = 0.f;
#pragma unroll
        for (int c = 0; c < NCHUNK; c++)
            s += g_ks_part[(bh * NCHUNK + c) * DIM + tid];
        g_ks[bh * DIM + tid] = s;
    }
}

// ---------------------------------------------------------------------------
// Phase 2: out = relu(Q) @ kv, normalized by max(relu(Q)·ksum, 1e-6).
// Block: 128 threads, P2ROWS=64 s-rows; thread tile 4(rows) x 8(cols).
// ---------------------------------------------------------------------------
__global__ __launch_bounds__(128) void la_phase2(const float* __restrict__ Q,
                                                 float* __restrict__ O) {
    const int bh = blockIdx.x;
    const int rb = blockIdx.y;    // 0 .. SEQ/P2ROWS-1
    const float* Qh = Q + (size_t)bh * SEQ * DIM + (size_t)rb * P2ROWS * DIM;
    float* Oh       = O + (size_t)bh * SEQ * DIM + (size_t)rb * P2ROWS * DIM;

    __shared__ float kvs[DIM][DIM];        // 16 KB
    __shared__ float qs[P2ROWS][DIM + 4];  // padded stride 68 -> no bank conflicts
    __shared__ float kss[DIM];

    const int tid = threadIdx.x;

    // Load kv (fits: 1024 float4 / 128 thr = 8 each)
    const float4* kvg = (const float4*)(g_kv + (size_t)bh * DIM * DIM);
#pragma unroll
    for (int l = 0; l < 8; l++)
        ((float4*)&kvs[0][0])[l * 128 + tid] = kvg[l * 128 + tid];
    if (tid < DIM) kss[tid] = g_ks[bh * DIM + tid];

    // Stage relu(Q): 64 rows x 16 float4 = 1024 float4 / 128 thr = 8 each
#pragma unroll
    for (int l = 0; l < 8; l++) {
        int idx = l * 128 + tid;
        int row = idx >> 4;
        int c4  = idx & 15;
        float4 q = ((const float4*)(Qh + (size_t)row * DIM))[c4];
        q.x = fmaxf(q.x, 0.f); q.y = fmaxf(q.y, 0.f);
        q.z = fmaxf(q.z, 0.f); q.w = fmaxf(q.w, 0.f);
        *(float4*)&qs[row][c4 * 4] = q;
    }
    __syncthreads();

    const int tx = tid & 7;    // col group: cols tx*8 ..
    const int ty = tid >> 3;   // row group: rows ty*4 .. (0..15)

    float acc[4][8];
    float nrm[4] = {0.f, 0.f, 0.f, 0.f};
#pragma unroll
    for (int i = 0; i < 4; i++)
#pragma unroll
        for (int j = 0; j < 8; j++) acc[i][j] = 0.f;

#pragma unroll
    for (int d0 = 0; d0 < DIM; d0 += 4) {
        float qf[4][4];
#pragma unroll
        for (int i = 0; i < 4; i++)
            *(float4*)&qf[i][0] = *(const float4*)&qs[ty * 4 + i][d0];
        float ksf[4];
        *(float4*)&ksf[0] = *(const float4*)&kss[d0];

#pragma unroll
        for (int dd = 0; dd < 4; dd++) {
            float4 a = *(const float4*)&kvs[d0 + dd][tx * 8];
            float4 b = *(const float4*)&kvs[d0 + dd][tx * 8 + 4];
            float vv[8] = {a.x, a.y, a.z, a.w, b.x, b.y, b.z, b.w};
#pragma unroll
            for (int i = 0; i < 4; i++) {
                float qv = qf[i][dd];
#pragma unroll
                for (int j = 0; j < 8; j++)
                    acc[i][j] = fmaf(qv, vv[j], acc[i][j]);
                nrm[i] = fmaf(qv, ksf[dd], nrm[i]);
            }
        }
    }

#pragma unroll
    for (int i = 0; i < 4; i++) {
        float inv = 1.f / fmaxf(nrm[i], 1e-6f);
        int row = ty * 4 + i;
        float4 w0 = make_float4(acc[i][0] * inv, acc[i][1] * inv,
                                acc[i][2] * inv, acc[i][3] * inv);
        float4 w1 = make_float4(acc[i][4] * inv, acc[i][5] * inv,
                                acc[i][6] * inv, acc[i][7] * inv);
        *(float4*)&Oh[(size_t)row * DIM + tx * 8]     = w0;
        *(float4*)&Oh[(size_t)row * DIM + tx * 8 + 4] = w1;
    }
}

// ---------------------------------------------------------------------------
extern "C" void kernel_launch(void* const* d_in, const int* in_sizes, int n_in,
                              void* d_out, int out_size) {
    const float* q = (const float*)d_in[0];
    const float* k = (const float*)d_in[1];
    const float* v = (const float*)d_in[2];
    float* o = (float*)d_out;

    dim3 g1(BH, NCHUNK);
    la_phase1<<<g1, 128>>>(k, v);
    la_reduce<<<BH, 256>>>();
    dim3 g2(BH, SEQ / P2ROWS);
    la_phase2<<<g2, 128>>>(q, o);
}

// round 2
// speedup vs baseline: 1.3511x; 1.3511x over previous
#include <cuda_runtime.h>
#include <cstdint>

#define BH     64
#define SEQ    8192
#define DIM    64
#define NCHUNK 32
#define CHUNK  (SEQ / NCHUNK)   // 256
#define TS     16
#define NT     (CHUNK / TS)     // 16
#define P2ROWS 128

typedef unsigned long long u64;

// Scratch (allocation-free: __device__ globals)
__device__ float g_kv_part[BH * NCHUNK * DIM * DIM];  // 32 MB
__device__ float g_ks_part[BH * NCHUNK * DIM];
__device__ float g_kv[BH * DIM * DIM];
__device__ float g_ks[BH * DIM];

// ---- packed f32x2 helpers -------------------------------------------------
__device__ __forceinline__ u64 pack2(float lo, float hi) {
    u64 r;
    asm("mov.b64 %0, {%1, %2};" : "=l"(r) : "f"(lo), "f"(hi));
    return r;
}
__device__ __forceinline__ void unpack2(u64 v, float& lo, float& hi) {
    asm("mov.b64 {%0, %1}, %2;" : "=f"(lo), "=f"(hi) : "l"(v));
}
__device__ __forceinline__ void fma2(u64& d, u64 a, u64 b) {
    asm("fma.rn.f32x2 %0, %1, %2, %0;" : "+l"(d) : "l"(a), "l"(b));
}
// ---- cp.async helpers -------------------------------------------------------
__device__ __forceinline__ void cp16(void* s, const void* g) {
    uint32_t sa = (uint32_t)__cvta_generic_to_shared(s);
    asm volatile("cp.async.cg.shared.global [%0], [%1], 16;"
                 :: "r"(sa), "l"(g) : "memory");
}
#define CP_COMMIT() asm volatile("cp.async.commit_group;" ::: "memory")
#define CP_WAIT1()  asm volatile("cp.async.wait_group 1;" ::: "memory")

// ---------------------------------------------------------------------------
// Phase 1: partial kv = relu(K)^T @ V, ksum = sum relu(K), per (head, chunk).
// 64 threads, 8x8 register tiles, f32x2 FMA, cp.async double-buffered tiles.
// ---------------------------------------------------------------------------
__global__ __launch_bounds__(64) void la_phase1(const float* __restrict__ K,
                                                const float* __restrict__ V) {
    const int bh = blockIdx.x, chunk = blockIdx.y;
    const float* Kh = K + (size_t)bh * SEQ * DIM + (size_t)chunk * CHUNK * DIM;
    const float* Vh = V + (size_t)bh * SEQ * DIM + (size_t)chunk * CHUNK * DIM;

    __shared__ float Ks[2][TS][DIM];
    __shared__ float Vs[2][TS][DIM];

    const int t  = threadIdx.x;
    const int tx = t & 7;    // e cols tx*8 .. +7
    const int ty = t >> 3;   // d rows ty*8 .. +7

    // copy slots: 256 float4 per array per tile, 64 threads -> 4 each
    int crow[4], ccol[4];
#pragma unroll
    for (int l = 0; l < 4; l++) {
        int idx = l * 64 + t;
        crow[l] = idx >> 4;
        ccol[l] = (idx & 15) * 4;
    }

    u64 acc[8][4];
    float ksum[8];
#pragma unroll
    for (int i = 0; i < 8; i++) {
        ksum[i] = 0.f;
#pragma unroll
        for (int j = 0; j < 4; j++) acc[i][j] = 0ull;
    }

    // prologue: prefetch tiles 0 and 1
#pragma unroll
    for (int p = 0; p < 2; p++) {
#pragma unroll
        for (int l = 0; l < 4; l++) {
            cp16(&Ks[p][crow[l]][ccol[l]],
                 Kh + (size_t)(p * TS + crow[l]) * DIM + ccol[l]);
            cp16(&Vs[p][crow[l]][ccol[l]],
                 Vh + (size_t)(p * TS + crow[l]) * DIM + ccol[l]);
        }
        CP_COMMIT();
    }

    for (int tl = 0; tl < NT; tl++) {
        CP_WAIT1();
        __syncthreads();
        const int b = tl & 1;

#pragma unroll 8
        for (int s = 0; s < TS; s++) {
            float4 ka = *(const float4*)&Ks[b][s][ty * 8];
            float4 kb = *(const float4*)&Ks[b][s][ty * 8 + 4];
            ulonglong2 va = *(const ulonglong2*)&Vs[b][s][tx * 8];
            ulonglong2 vb = *(const ulonglong2*)&Vs[b][s][tx * 8 + 4];
            float kf[8] = {ka.x, ka.y, ka.z, ka.w, kb.x, kb.y, kb.z, kb.w};
#pragma unroll
            for (int i = 0; i < 8; i++) {
                float km = fmaxf(kf[i], 0.f);
                ksum[i] += km;
                u64 k2 = pack2(km, km);
                fma2(acc[i][0], k2, va.x);
                fma2(acc[i][1], k2, va.y);
                fma2(acc[i][2], k2, vb.x);
                fma2(acc[i][3], k2, vb.y);
            }
        }
        __syncthreads();

        if (tl + 2 < NT) {
#pragma unroll
            for (int l = 0; l < 4; l++) {
                cp16(&Ks[b][crow[l]][ccol[l]],
                     Kh + (size_t)((tl + 2) * TS + crow[l]) * DIM + ccol[l]);
                cp16(&Vs[b][crow[l]][ccol[l]],
                     Vh + (size_t)((tl + 2) * TS + crow[l]) * DIM + ccol[l]);
            }
        }
        CP_COMMIT();   // empty groups at tail keep wait_group bookkeeping sound
    }

    float* kvp = g_kv_part + ((size_t)bh * NCHUNK + chunk) * DIM * DIM;
#pragma unroll
    for (int i = 0; i < 8; i++) {
        int d = ty * 8 + i;
        float o0, o1, o2, o3, o4, o5, o6, o7;
        unpack2(acc[i][0], o0, o1);
        unpack2(acc[i][1], o2, o3);
        unpack2(acc[i][2], o4, o5);
        unpack2(acc[i][3], o6, o7);
        *(float4*)&kvp[d * DIM + tx * 8]     = make_float4(o0, o1, o2, o3);
        *(float4*)&kvp[d * DIM + tx * 8 + 4] = make_float4(o4, o5, o6, o7);
    }
    if (tx == 0) {
#pragma unroll
        for (int i = 0; i < 8; i++)
            g_ks_part[((size_t)bh * NCHUNK + chunk) * DIM + ty * 8 + i] = ksum[i];
    }
}

// ---------------------------------------------------------------------------
// Reduce partials -> g_kv, g_ks
// ---------------------------------------------------------------------------
__global__ __launch_bounds__(256) void la_reduce() {
    const int bh  = blockIdx.x;
    const int tid = threadIdx.x;
    for (int idx = tid; idx < DIM * DIM; idx += 256) {
        float sum = 0.f;
#pragma unroll
        for (int c = 0; c < NCHUNK; c++)
            sum += g_kv_part[((size_t)bh * NCHUNK + c) * DIM * DIM + idx];
        g_kv[(size_t)bh * DIM * DIM + idx] = sum;
    }
    if (tid < DIM) {
        float s = 0.f;
#pragma unroll
        for (int c = 0; c < NCHUNK; c++)
            s += g_ks_part[((size_t)bh * NCHUNK + c) * DIM + tid];
        g_ks[bh * DIM + tid] = s;
    }
}

// ---------------------------------------------------------------------------
// Phase 2: out = relu(Q) @ kv / max(relu(Q)·ksum, 1e-6).
// 128 threads, 128x64 block tile, 8x8 per thread, f32x2 FMA.
// Q staged in two 32-d-column passes (keeps static smem < 48 KB).
// ---------------------------------------------------------------------------
__global__ __launch_bounds__(128) void la_phase2(const float* __restrict__ Q,
                                                 float* __restrict__ O) {
    const int bh = blockIdx.x;
    const int rb = blockIdx.y;
    const float* Qh = Q + (size_t)bh * SEQ * DIM + (size_t)rb * P2ROWS * DIM;
    float* Oh       = O + (size_t)bh * SEQ * DIM + (size_t)rb * P2ROWS * DIM;

    __shared__ float kvs[DIM][DIM];       // 16 KB
    __shared__ float qs[P2ROWS][32];      // 16 KB (half of d at a time)
    __shared__ float kss[DIM];

    const int tid = threadIdx.x;
    const int tx  = tid & 7;    // e cols tx*8 .. +7
    const int ty  = tid >> 3;   // s rows ty*8 .. +7 (ty 0..15)

    // load kv (1024 float4 / 128 threads = 8 each) + ksum
    const float4* kvg = (const float4*)(g_kv + (size_t)bh * DIM * DIM);
#pragma unroll
    for (int l = 0; l < 8; l++)
        ((float4*)&kvs[0][0])[l * 128 + tid] = kvg[l * 128 + tid];
    if (tid < DIM) kss[tid] = g_ks[bh * DIM + tid];

    u64 acc[8][4];
    u64 nrm2[8];
#pragma unroll
    for (int i = 0; i < 8; i++) {
        nrm2[i] = 0ull;
#pragma unroll
        for (int j = 0; j < 4; j++) acc[i][j] = 0ull;
    }

#pragma unroll
    for (int pass = 0; pass < 2; pass++) {
        __syncthreads();
        // stage relu(Q) columns [pass*32, pass*32+32): 1024 float4 / 128 thr = 8
#pragma unroll
        for (int l = 0; l < 8; l++) {
            int idx = l * 128 + tid;
            int row = idx >> 3;
            int c4  = (idx & 7) * 4;
            float4 q = *(const float4*)(Qh + (size_t)row * DIM + pass * 32 + c4);
            q.x = fmaxf(q.x, 0.f); q.y = fmaxf(q.y, 0.f);
            q.z = fmaxf(q.z, 0.f); q.w = fmaxf(q.w, 0.f);
            *(float4*)&qs[row][c4] = q;
        }
        __syncthreads();

#pragma unroll 2
        for (int d0 = pass * 32; d0 < pass * 32 + 32; d0 += 4) {
            float4 ks4 = *(const float4*)&kss[d0];
            u64 ks2a = pack2(ks4.x, ks4.y);
            u64 ks2b = pack2(ks4.z, ks4.w);
            ulonglong2 kv_[4][2];
#pragma unroll
            for (int dd = 0; dd < 4; dd++) {
                kv_[dd][0] = *(const ulonglong2*)&kvs[d0 + dd][tx * 8];
                kv_[dd][1] = *(const ulonglong2*)&kvs[d0 + dd][tx * 8 + 4];
            }
#pragma unroll
            for (int i = 0; i < 8; i++) {
                float4 q4 = *(const float4*)&qs[ty * 8 + i][d0 - pass * 32];
                fma2(nrm2[i], pack2(q4.x, q4.y), ks2a);
                fma2(nrm2[i], pack2(q4.z, q4.w), ks2b);
                u64 q0 = pack2(q4.x, q4.x);
                u64 q1 = pack2(q4.y, q4.y);
                u64 q2 = pack2(q4.z, q4.z);
                u64 q3 = pack2(q4.w, q4.w);
                fma2(acc[i][0], q0, kv_[0][0].x); fma2(acc[i][1], q0, kv_[0][0].y);
                fma2(acc[i][2], q0, kv_[0][1].x); fma2(acc[i][3], q0, kv_[0][1].y);
                fma2(acc[i][0], q1, kv_[1][0].x); fma2(acc[i][1], q1, kv_[1][0].y);
                fma2(acc[i][2], q1, kv_[1][1].x); fma2(acc[i][3], q1, kv_[1][1].y);
                fma2(acc[i][0], q2, kv_[2][0].x); fma2(acc[i][1], q2, kv_[2][0].y);
                fma2(acc[i][2], q2, kv_[2][1].x); fma2(acc[i][3], q2, kv_[2][1].y);
                fma2(acc[i][0], q3, kv_[3][0].x); fma2(acc[i][1], q3, kv_[3][0].y);
                fma2(acc[i][2], q3, kv_[3][1].x); fma2(acc[i][3], q3, kv_[3][1].y);
            }
        }
    }

#pragma unroll
    for (int i = 0; i < 8; i++) {
        float nl, nh;
        unpack2(nrm2[i], nl, nh);
        float inv = 1.f / fmaxf(nl + nh, 1e-6f);
        float o0, o1, o2, o3, o4, o5, o6, o7;
        unpack2(acc[i][0], o0, o1);
        unpack2(acc[i][1], o2, o3);
        unpack2(acc[i][2], o4, o5);
        unpack2(acc[i][3], o6, o7);
        int row = ty * 8 + i;
        *(float4*)&Oh[(size_t)row * DIM + tx * 8] =
            make_float4(o0 * inv, o1 * inv, o2 * inv, o3 * inv);
        *(float4*)&Oh[(size_t)row * DIM + tx * 8 + 4] =
            make_float4(o4 * inv, o5 * inv, o6 * inv, o7 * inv);
    }
}

// ---------------------------------------------------------------------------
extern "C" void kernel_launch(void* const* d_in, const int* in_sizes, int n_in,
                              void* d_out, int out_size) {
    const float* q = (const float*)d_in[0];
    const float* k = (const float*)d_in[1];
    const float* v = (const float*)d_in[2];
    float* o = (float*)d_out;

    la_phase1<<<dim3(BH, NCHUNK), 64>>>(k, v);
    la_reduce<<<BH, 256>>>();
    la_phase2<<<dim3(BH, SEQ / P2ROWS), 128>>>(q, o);
}